// round 4
// baseline (speedup 1.0000x reference)
#include <cuda_runtime.h>
#include <cstddef>

#define NGN 100000
#define NDN 100000
#define NE  400000
#define NEL 200000
#define CC  128

#define MT 128          // rows per block
#define KC 16           // k-chunk
#define NCHUNK (CC / KC)
#define ADUP_STRIDE 264 // floats per k-row of duplicated A (256 data + pad, 16B-mult)

// packed f32x2 FMA: d = a*b + d (elementwise on 2-float pairs in 64-bit regs)
#define FMA2(d, a, b) \
    asm("fma.rn.f32x2 %0, %1, %2, %0;" : "+l"(d) : "l"(a), "l"(b))

// Scratch (device globals; no allocation allowed in kernel_launch)
__device__ __align__(16) float g_ug[(size_t)NGN * CC];
__device__ __align__(16) float g_ud[(size_t)NDN * CC];
__device__ unsigned char g_mask_g[NGN];
__device__ unsigned char g_mask_d[NDN];

// ---------------------------------------------------------------------------
__global__ void init_masks_kernel() {
    int i = blockIdx.x * blockDim.x + threadIdx.x;
    if (i < NGN) g_mask_g[i] = 0;
    if (i < NDN) g_mask_d[i] = 0;
}

__global__ void scatter_masks_kernel(const int* __restrict__ dst_g2d,
                                     const int* __restrict__ dst_d2g) {
    int e = blockIdx.x * blockDim.x + threadIdx.x;
    if (e < NE) {
        g_mask_d[dst_g2d[e]] = 1;   // g2d edges land on diseases
        g_mask_g[dst_d2g[e]] = 1;   // d2g edges land on genes
    }
}

// ---------------------------------------------------------------------------
// GEMM: out[M,128] = act(A[M,128] @ W[128,128] + bias) (* mask if do_relu)
// 128x128 tile, 256 threads, 8x8 microtile computed as 8x4 packed f32x2 FMAs.
// A stored k-major AND element-duplicated in smem so a-fragments load as
// LDS.128 of (a,a) pairs; w-pairs are natural LDS.128 of ws[k][n].
// ---------------------------------------------------------------------------
__global__ __launch_bounds__(256, 2) void gemm128_kernel(
    const float* __restrict__ A, const float* __restrict__ W,
    const float* __restrict__ bias, const unsigned char* __restrict__ mask,
    float* __restrict__ out, int M, int do_relu)
{
    __shared__ float as_dup[KC][ADUP_STRIDE];  // [k][2*row] duplicated pairs (~16.5KB)
    __shared__ float ws[KC][CC];               // [k][n] (8KB)

    const int tid = threadIdx.x;
    const int tx = tid & 15;               // 16 col groups (8 cols)
    const int ty = tid >> 4;               // 16 row groups (8 rows)
    const int row0 = blockIdx.x * MT;

    // A staging map: 128 rows x 16 k = 512 float4; 2 per thread
    const int ar = tid >> 2;               // 0..63 (and +64)
    const int ak = (tid & 3) << 2;         // 0,4,8,12
    // W staging map: 16 k x 128 n = 512 float4; 2 per thread
    const int wk = tid >> 5;               // 0..7 (and +8)
    const int wn = (tid & 31) << 2;        // 0..124

    unsigned long long acc2[8][4];
    #pragma unroll
    for (int i = 0; i < 8; ++i)
        #pragma unroll
        for (int j = 0; j < 4; ++j) acc2[i][j] = 0ULL;

    float4 pa[2], pw[2];

    // prefetch chunk 0
    #pragma unroll
    for (int t = 0; t < 2; ++t) {
        int r = ar + t * 64;
        pa[t] = make_float4(0.f, 0.f, 0.f, 0.f);
        if (row0 + r < M)
            pa[t] = *(const float4*)(A + (size_t)(row0 + r) * CC + ak);
        pw[t] = *(const float4*)(W + (size_t)(wk + t * 8) * CC + wn);
    }

    #pragma unroll
    for (int c = 0; c < NCHUNK; ++c) {
        // commit prefetched registers to smem (A duplicated per element)
        #pragma unroll
        for (int t = 0; t < 2; ++t) {
            int r2 = (ar + t * 64) * 2;
            *(float2*)&as_dup[ak + 0][r2] = make_float2(pa[t].x, pa[t].x);
            *(float2*)&as_dup[ak + 1][r2] = make_float2(pa[t].y, pa[t].y);
            *(float2*)&as_dup[ak + 2][r2] = make_float2(pa[t].z, pa[t].z);
            *(float2*)&as_dup[ak + 3][r2] = make_float2(pa[t].w, pa[t].w);
            *(float4*)&ws[wk + t * 8][wn] = pw[t];
        }
        __syncthreads();

        // prefetch next chunk
        if (c < NCHUNK - 1) {
            int kc = (c + 1) * KC;
            #pragma unroll
            for (int t = 0; t < 2; ++t) {
                int r = ar + t * 64;
                pa[t] = make_float4(0.f, 0.f, 0.f, 0.f);
                if (row0 + r < M)
                    pa[t] = *(const float4*)(A + (size_t)(row0 + r) * CC + kc + ak);
                pw[t] = *(const float4*)(W + (size_t)(kc + wk + t * 8) * CC + wn);
            }
        }

        #pragma unroll
        for (int k = 0; k < KC; ++k) {
            // a-fragment: 8 duplicated pairs = 4 x LDS.128 (broadcast within warp)
            const ulonglong2 a01 = *(const ulonglong2*)&as_dup[k][ty * 16];
            const ulonglong2 a23 = *(const ulonglong2*)&as_dup[k][ty * 16 + 4];
            const ulonglong2 a45 = *(const ulonglong2*)&as_dup[k][ty * 16 + 8];
            const ulonglong2 a67 = *(const ulonglong2*)&as_dup[k][ty * 16 + 12];
            // w-fragment: 4 natural pairs = 2 x LDS.128
            const ulonglong2 w03 = *(const ulonglong2*)&ws[k][tx * 8];
            const ulonglong2 w47 = *(const ulonglong2*)&ws[k][tx * 8 + 4];

            const unsigned long long av[8] =
                {a01.x, a01.y, a23.x, a23.y, a45.x, a45.y, a67.x, a67.y};
            const unsigned long long wv[4] = {w03.x, w03.y, w47.x, w47.y};

            #pragma unroll
            for (int i = 0; i < 8; ++i) {
                FMA2(acc2[i][0], av[i], wv[0]);
                FMA2(acc2[i][1], av[i], wv[1]);
                FMA2(acc2[i][2], av[i], wv[2]);
                FMA2(acc2[i][3], av[i], wv[3]);
            }
        }
        __syncthreads();
    }

    // Epilogue
    float bv[8];
    #pragma unroll
    for (int j = 0; j < 8; ++j)
        bv[j] = bias ? bias[tx * 8 + j] : 0.0f;

    #pragma unroll
    for (int i = 0; i < 8; ++i) {
        int r = row0 + ty * 8 + i;
        if (r < M) {
            float mm = 1.0f;
            if (do_relu && mask) mm = (float)mask[r];
            float o[8];
            #pragma unroll
            for (int jp = 0; jp < 4; ++jp) {
                unsigned long long v = acc2[i][jp];
                o[2 * jp]     = __uint_as_float((unsigned)(v & 0xFFFFFFFFu));
                o[2 * jp + 1] = __uint_as_float((unsigned)(v >> 32));
            }
            #pragma unroll
            for (int j = 0; j < 8; ++j) {
                float v = o[j] + bv[j];
                if (do_relu) v = fmaxf(v, 0.0f) * mm;
                o[j] = v;
            }
            float* dst = out + (size_t)r * CC + tx * 8;
            *(float4*)dst       = make_float4(o[0], o[1], o[2], o[3]);
            *(float4*)(dst + 4) = make_float4(o[4], o[5], o[6], o[7]);
        }
    }
}

// ---------------------------------------------------------------------------
// Link prediction head: one warp per labeled edge.
// pred[e] = relu(u_g[row[e]] + u_d[col[e]]) . W2 + b2     (b1 folded into u_d)
// ---------------------------------------------------------------------------
__global__ __launch_bounds__(256) void pred_kernel(
    const int* __restrict__ erow, const int* __restrict__ ecol,
    const float* __restrict__ W2, const float* __restrict__ b2,
    float* __restrict__ pred)
{
    int warp = (blockIdx.x * blockDim.x + threadIdx.x) >> 5;
    int lane = threadIdx.x & 31;
    if (warp >= NEL) return;

    int r = erow[warp];
    int c = ecol[warp];
    const float4 ug = *(const float4*)(g_ug + (size_t)r * CC + lane * 4);
    const float4 ud = *(const float4*)(g_ud + (size_t)c * CC + lane * 4);
    const float4 w2 = *(const float4*)(W2 + lane * 4);

    float s = fmaxf(ug.x + ud.x, 0.f) * w2.x
            + fmaxf(ug.y + ud.y, 0.f) * w2.y
            + fmaxf(ug.z + ud.z, 0.f) * w2.z
            + fmaxf(ug.w + ud.w, 0.f) * w2.w;

    #pragma unroll
    for (int o = 16; o > 0; o >>= 1)
        s += __shfl_xor_sync(0xFFFFFFFFu, s, o);

    if (lane == 0) pred[warp] = s + b2[0];
}

// ---------------------------------------------------------------------------
extern "C" void kernel_launch(void* const* d_in, const int* in_sizes, int n_in,
                              void* d_out, int out_size)
{
    (void)in_sizes; (void)n_in; (void)out_size;

    const float* x_gene    = (const float*)d_in[0];
    const float* x_disease = (const float*)d_in[1];
    const int*   ei_g2d    = (const int*)d_in[2];   // [2, E]: row0 src, row1 dst
    const int*   ei_d2g    = (const int*)d_in[3];
    const int*   eli       = (const int*)d_in[6];   // [2, EL]
    const float* Wn_g      = (const float*)d_in[7];
    const float* bn_g      = (const float*)d_in[8];
    const float* Wn_d      = (const float*)d_in[9];
    const float* bn_d      = (const float*)d_in[10];
    const float* W1        = (const float*)d_in[17];  // [256, 128]
    const float* b1        = (const float*)d_in[18];
    const float* W2        = (const float*)d_in[19];  // [128, 1]
    const float* b2        = (const float*)d_in[20];

    float* out   = (float*)d_out;
    float* pred  = out;                                // [EL]
    float* z_gen = out + NEL;                          // [NG, 128]
    float* z_dis = out + NEL + (size_t)NGN * CC;       // [ND, 128]

    float* ug_ptr; float* ud_ptr;
    unsigned char* mg_ptr; unsigned char* md_ptr;
    cudaGetSymbolAddress((void**)&ug_ptr, g_ug);
    cudaGetSymbolAddress((void**)&ud_ptr, g_ud);
    cudaGetSymbolAddress((void**)&mg_ptr, g_mask_g);
    cudaGetSymbolAddress((void**)&md_ptr, g_mask_d);

    // 1) isolation masks
    init_masks_kernel<<<(NGN + 255) / 256, 256>>>();
    scatter_masks_kernel<<<(NE + 255) / 256, 256>>>(ei_g2d + NE, ei_d2g + NE);

    const int grid_g = (NGN + MT - 1) / MT;
    const int grid_d = (NDN + MT - 1) / MT;

    // Order for L2 reuse: consume each z right after producing it.
    gemm128_kernel<<<grid_g, 256>>>(x_gene,    Wn_g, bn_g, mg_ptr, z_gen, NGN, 1);
    gemm128_kernel<<<grid_g, 256>>>(z_gen, W1,           nullptr, nullptr, ug_ptr, NGN, 0);
    gemm128_kernel<<<grid_d, 256>>>(x_disease, Wn_d, bn_d, md_ptr, z_dis, NDN, 1);
    gemm128_kernel<<<grid_d, 256>>>(z_dis, W1 + CC * CC, b1,      nullptr, ud_ptr, NDN, 0);

    // 4) edge scores
    pred_kernel<<<(NEL * 32 + 255) / 256, 256>>>(eli, eli + NEL, W2, b2, pred);
}

// round 6
// speedup vs baseline: 1.8469x; 1.8469x over previous
#include <cuda_runtime.h>
#include <cuda_bf16.h>
#include <cstdint>
#include <cstddef>

#define NGN 100000
#define NDN 100000
#define NE  400000
#define NEL 200000
#define CC  128
#define TM  128
#define TILES ((NGN + TM - 1) / TM)      // 782
#define CHUNK_ELEMS 8192                 // 128 rows * 64 bf16 = 16KB
#define TILE_IMG_ELEMS (2 * CHUNK_ELEMS) // 32KB image (2 chunks)

// smem layout (bytes): A-hi, A-lo (reused for Z-hi/Z-lo), W-stage1 hi/lo, W-stage2 hi/lo
#define SM_AH   0
#define SM_AL   32768
#define SM_W1H  65536
#define SM_W1L  98304
#define SM_W2H  131072
#define SM_W2L  163840
#define SMEM_TOTAL 196608

// ---------------------------------------------------------------------------
// Device globals (no allocation allowed in kernel_launch)
__device__ __align__(16) __nv_bfloat16 g_wimg[4][2][TILE_IMG_ELEMS]; // [mat][hi/lo]
__device__ __align__(16) float g_ug[(size_t)NGN * CC];
__device__ __align__(16) float g_ud[(size_t)NDN * CC];
__device__ unsigned char g_mask_g[NGN];
__device__ unsigned char g_mask_d[NDN];

// ---------------------------------------------------------------------------
__device__ __forceinline__ uint32_t smem_u32(const void* p) {
    uint32_t a;
    asm("{ .reg .u64 t; cvta.to.shared.u64 t, %1; cvt.u32.u64 %0, t; }"
        : "=r"(a) : "l"(p));
    return a;
}
__device__ __forceinline__ uint32_t swz(uint32_t off) {   // SW128 swizzle
    return off ^ ((off >> 3) & 0x70);
}

#define LDSM_X4(r0, r1, r2, r3, addr) \
    asm volatile("ldmatrix.sync.aligned.m8n8.x4.shared.b16 {%0,%1,%2,%3}, [%4];" \
        : "=r"(r0), "=r"(r1), "=r"(r2), "=r"(r3) : "r"(addr))

#define MMA16816(c, a, b) \
    asm volatile("mma.sync.aligned.m16n8k16.row.col.f32.bf16.bf16.f32 " \
        "{%0,%1,%2,%3}, {%4,%5,%6,%7}, {%8,%9}, {%0,%1,%2,%3};" \
        : "+f"((c)[0]), "+f"((c)[1]), "+f"((c)[2]), "+f"((c)[3]) \
        : "r"((a)[0]), "r"((a)[1]), "r"((a)[2]), "r"((a)[3]), \
          "r"((b)[0]), "r"((b)[1]))

// split fp32 -> bf16 hi + bf16 lo (residual)
__device__ __forceinline__ void split4(const float4 v, uint2& hv, uint2& lv) {
    __nv_bfloat16 h0 = __float2bfloat16(v.x), h1 = __float2bfloat16(v.y);
    __nv_bfloat16 h2 = __float2bfloat16(v.z), h3 = __float2bfloat16(v.w);
    float l0 = v.x - __bfloat162float(h0), l1 = v.y - __bfloat162float(h1);
    float l2 = v.z - __bfloat162float(h2), l3 = v.w - __bfloat162float(h3);
    __nv_bfloat162 hp0(h0, h1), hp1(h2, h3);
    __nv_bfloat162 lp0(__float2bfloat16(l0), __float2bfloat16(l1));
    __nv_bfloat162 lp1(__float2bfloat16(l2), __float2bfloat16(l3));
    hv.x = *(uint32_t*)&hp0; hv.y = *(uint32_t*)&hp1;
    lv.x = *(uint32_t*)&lp0; lv.y = *(uint32_t*)&lp1;
}
__device__ __forceinline__ void split2(float v0, float v1, uint32_t& h, uint32_t& l) {
    __nv_bfloat16 h0 = __float2bfloat16(v0), h1 = __float2bfloat16(v1);
    float l0 = v0 - __bfloat162float(h0), l1 = v1 - __bfloat162float(h1);
    __nv_bfloat162 hp(h0, h1);
    __nv_bfloat162 lp(__float2bfloat16(l0), __float2bfloat16(l1));
    h = *(uint32_t*)&hp; l = *(uint32_t*)&lp;
}

// ---------------------------------------------------------------------------
__global__ void init_masks_kernel() {
    int i = blockIdx.x * blockDim.x + threadIdx.x;
    if (i < NGN) g_mask_g[i] = 0;
    if (i < NDN) g_mask_d[i] = 0;
}
__global__ void scatter_masks_kernel(const int* __restrict__ dst_g2d,
                                     const int* __restrict__ dst_d2g) {
    int e = blockIdx.x * blockDim.x + threadIdx.x;
    if (e < NE) {
        g_mask_d[dst_g2d[e]] = 1;
        g_mask_g[dst_d2g[e]] = 1;
    }
}

// ---------------------------------------------------------------------------
// W split: W[128,128] (K x N, row-major) -> W^T image [n][k] bf16 hi/lo,
// chunked (k 0..63 / 64..127), SW128-swizzled 128B rows.
// block b: 0=Wn_g 1=Wn_d 2=W1[:128] 3=W1[128:]
// ---------------------------------------------------------------------------
__global__ __launch_bounds__(256) void wsplit_kernel(
    const float* __restrict__ Wg, const float* __restrict__ Wd,
    const float* __restrict__ W1)
{
    const float* W = (blockIdx.x == 0) ? Wg : (blockIdx.x == 1) ? Wd
                   : (blockIdx.x == 2) ? W1 : (W1 + CC * CC);
    int n = threadIdx.x >> 1;
    int c = threadIdx.x & 1;
    char* ph = (char*)&g_wimg[blockIdx.x][0][(size_t)c * CHUNK_ELEMS];
    char* pl = (char*)&g_wimg[blockIdx.x][1][(size_t)c * CHUNK_ELEMS];
    #pragma unroll
    for (int kk = 0; kk < 64; kk += 4) {
        int k = c * 64 + kk;
        float4 v = make_float4(W[(size_t)(k + 0) * CC + n], W[(size_t)(k + 1) * CC + n],
                               W[(size_t)(k + 2) * CC + n], W[(size_t)(k + 3) * CC + n]);
        uint2 hv, lv;
        split4(v, hv, lv);
        uint32_t off = swz((uint32_t)(n * 128 + kk * 2));
        *(uint2*)(ph + off) = hv;
        *(uint2*)(pl + off) = lv;
    }
}

// ---------------------------------------------------------------------------
// 3-pass split-bf16 MMA over one 128x128x128 stage.
// A image at (abh/abl), B image (W^T) at (bbh/bbl). acc += A @ W.
// ---------------------------------------------------------------------------
__device__ __forceinline__ void mma_stage(
    uint32_t abh, uint32_t abl, uint32_t bbh, uint32_t bbl,
    int wm, int wn, int lane, float acc[4][4][4])
{
    const int g = lane >> 3;
    const int r7 = lane & 7;
    const int arow = ((g & 1) << 3) + r7;     // A: matrix pair -> +8 rows
    const int akseg = (g >> 1) << 4;          // A: -> +16 bytes (k+8)
    const int brow = ((g >> 1) << 3) + r7;    // B: -> +8 n
    const int bkseg = (g & 1) << 4;           // B: -> +16 bytes (k+8)

    #pragma unroll
    for (int p = 0; p < 3; ++p) {             // (Ah,Wh), (Ah,Wl), (Al,Wh)
        const uint32_t ab = (p == 2) ? abl : abh;
        const uint32_t bb = (p == 1) ? bbl : bbh;
        #pragma unroll
        for (int kt = 0; kt < 8; ++kt) {
            const uint32_t coff = (uint32_t)(kt >> 2) * 16384u;
            const int kb = (kt & 3) * 32;

            uint32_t a[4][4];
            #pragma unroll
            for (int mt = 0; mt < 4; ++mt) {
                int row = wm * 64 + mt * 16 + arow;
                uint32_t addr = ab + coff + swz((uint32_t)(row * 128 + kb + akseg));
                LDSM_X4(a[mt][0], a[mt][1], a[mt][2], a[mt][3], addr);
            }
            uint32_t b[4][2];
            #pragma unroll
            for (int h = 0; h < 2; ++h) {
                int n = wn * 32 + h * 16 + brow;
                uint32_t addr = bb + coff + swz((uint32_t)(n * 128 + kb + bkseg));
                uint32_t r0, r1, r2, r3;
                LDSM_X4(r0, r1, r2, r3, addr);
                b[h * 2][0] = r0;     b[h * 2][1] = r1;
                b[h * 2 + 1][0] = r2; b[h * 2 + 1][1] = r3;
            }
            #pragma unroll
            for (int mt = 0; mt < 4; ++mt)
                #pragma unroll
                for (int nt = 0; nt < 4; ++nt)
                    MMA16816(acc[mt][nt], a[mt], b[nt]);
        }
    }
}

// ---------------------------------------------------------------------------
// Fused per-tile kernel:
//   z = relu(x@Wa + bias1) * mask    (write fp32)
//   u = z@Wb (+ bias2)               (write fp32)
// ---------------------------------------------------------------------------
__global__ __launch_bounds__(256, 1) void fused_gemm_kernel(
    const float* __restrict__ X,
    const __nv_bfloat16* __restrict__ w1h, const __nv_bfloat16* __restrict__ w1l,
    const __nv_bfloat16* __restrict__ w2h, const __nv_bfloat16* __restrict__ w2l,
    const float* __restrict__ bias1, const float* __restrict__ bias2,
    const unsigned char* __restrict__ mask,
    float* __restrict__ zout, float* __restrict__ uout, int M)
{
    extern __shared__ char smem[];
    const uint32_t sb = smem_u32(smem);
    const int tid = threadIdx.x;
    const int lane = tid & 31;
    const int wid = tid >> 5;
    const int wm = wid >> 2;   // 2 m-halves of 64 rows
    const int wn = wid & 3;    // 4 n-quarters of 32 cols
    const int t = blockIdx.x;
    const int rows_left = M - t * TM;

    // ---- stage x -> bf16 hi/lo swizzled images; copy W images ----
    {
        const float4* xs = (const float4*)(X + (size_t)t * TM * CC);
        #pragma unroll
        for (int i = 0; i < 16; ++i) {
            int q = i * 256 + tid;          // float4 index within tile
            int row = q >> 5;
            int kk = (q & 31) << 2;         // float col (0..124)
            float4 v = (row < rows_left) ? xs[q] : make_float4(0.f, 0.f, 0.f, 0.f);
            uint2 hv, lv;
            split4(v, hv, lv);
            uint32_t off = (uint32_t)((kk >> 6) * 16384)
                         + swz((uint32_t)(row * 128 + (kk & 63) * 2));
            *(uint2*)(smem + SM_AH + off) = hv;
            *(uint2*)(smem + SM_AL + off) = lv;
        }
        const uint4* s[4] = {(const uint4*)w1h, (const uint4*)w1l,
                             (const uint4*)w2h, (const uint4*)w2l};
        uint4* d[4] = {(uint4*)(smem + SM_W1H), (uint4*)(smem + SM_W1L),
                       (uint4*)(smem + SM_W2H), (uint4*)(smem + SM_W2L)};
        #pragma unroll
        for (int bimg = 0; bimg < 4; ++bimg)
            #pragma unroll
            for (int i = 0; i < 8; ++i)
                d[bimg][i * 256 + tid] = s[bimg][i * 256 + tid];
    }
    __syncthreads();

    float acc[4][4][4];
    #pragma unroll
    for (int mt = 0; mt < 4; ++mt)
        #pragma unroll
        for (int nt = 0; nt < 4; ++nt)
            #pragma unroll
            for (int j = 0; j < 4; ++j) acc[mt][nt][j] = 0.0f;

    // ---- stage 1: z = x @ Wa ----
    mma_stage(sb + SM_AH, sb + SM_AL, sb + SM_W1H, sb + SM_W1L, wm, wn, lane, acc);
    __syncthreads();   // everyone done reading A images before we overwrite

    // ---- epilogue 1: bias + relu*mask, write z, re-split into A buffers ----
    const int row_base = t * TM;
    #pragma unroll
    for (int mt = 0; mt < 4; ++mt) {
        const int rl0 = wm * 64 + mt * 16 + (lane >> 2);
        #pragma unroll
        for (int nt = 0; nt < 4; ++nt) {
            const int col = wn * 32 + nt * 8 + 2 * (lane & 3);
            const float2 bv = *(const float2*)&bias1[col];
            #pragma unroll
            for (int hh = 0; hh < 2; ++hh) {
                const int rl = rl0 + hh * 8;
                const int r = row_base + rl;
                float v0 = acc[mt][nt][hh * 2 + 0] + bv.x;
                float v1 = acc[mt][nt][hh * 2 + 1] + bv.y;
                if (r < M) {
                    const float mmv = (float)mask[r];
                    v0 = fmaxf(v0, 0.0f) * mmv;
                    v1 = fmaxf(v1, 0.0f) * mmv;
                    *(float2*)(zout + (size_t)r * CC + col) = make_float2(v0, v1);
                    uint32_t h, l;
                    split2(v0, v1, h, l);
                    uint32_t off = (uint32_t)((col >> 6) * 16384)
                                 + swz((uint32_t)(rl * 128 + (col & 63) * 2));
                    *(uint32_t*)(smem + SM_AH + off) = h;
                    *(uint32_t*)(smem + SM_AL + off) = l;
                }
            }
        }
    }
    __syncthreads();

    // ---- stage 2: u = z @ Wb ----
    #pragma unroll
    for (int mt = 0; mt < 4; ++mt)
        #pragma unroll
        for (int nt = 0; nt < 4; ++nt)
            #pragma unroll
            for (int j = 0; j < 4; ++j) acc[mt][nt][j] = 0.0f;

    mma_stage(sb + SM_AH, sb + SM_AL, sb + SM_W2H, sb + SM_W2L, wm, wn, lane, acc);

    // ---- epilogue 2: (+bias2), write u ----
    #pragma unroll
    for (int mt = 0; mt < 4; ++mt) {
        const int rl0 = wm * 64 + mt * 16 + (lane >> 2);
        #pragma unroll
        for (int nt = 0; nt < 4; ++nt) {
            const int col = wn * 32 + nt * 8 + 2 * (lane & 3);
            float2 bv = bias2 ? *(const float2*)&bias2[col] : make_float2(0.f, 0.f);
            #pragma unroll
            for (int hh = 0; hh < 2; ++hh) {
                const int r = row_base + rl0 + hh * 8;
                if (r < M) {
                    float v0 = acc[mt][nt][hh * 2 + 0] + bv.x;
                    float v1 = acc[mt][nt][hh * 2 + 1] + bv.y;
                    *(float2*)(uout + (size_t)r * CC + col) = make_float2(v0, v1);
                }
            }
        }
    }
}

// ---------------------------------------------------------------------------
// Link prediction head: one warp per labeled edge.
// pred[e] = relu(u_g[row] + u_d[col]) . W2 + b2   (b1 folded into u_d)
// ---------------------------------------------------------------------------
__global__ __launch_bounds__(256) void pred_kernel(
    const int* __restrict__ erow, const int* __restrict__ ecol,
    const float* __restrict__ W2, const float* __restrict__ b2,
    float* __restrict__ pred)
{
    int warp = (blockIdx.x * blockDim.x + threadIdx.x) >> 5;
    int lane = threadIdx.x & 31;
    if (warp >= NEL) return;

    int r = erow[warp];
    int c = ecol[warp];
    const float4 ug = *(const float4*)(g_ug + (size_t)r * CC + lane * 4);
    const float4 ud = *(const float4*)(g_ud + (size_t)c * CC + lane * 4);
    const float4 w2 = *(const float4*)(W2 + lane * 4);

    float s = fmaxf(ug.x + ud.x, 0.f) * w2.x
            + fmaxf(ug.y + ud.y, 0.f) * w2.y
            + fmaxf(ug.z + ud.z, 0.f) * w2.z
            + fmaxf(ug.w + ud.w, 0.f) * w2.w;

    #pragma unroll
    for (int o = 16; o > 0; o >>= 1)
        s += __shfl_xor_sync(0xFFFFFFFFu, s, o);

    if (lane == 0) pred[warp] = s + b2[0];
}

// ---------------------------------------------------------------------------
extern "C" void kernel_launch(void* const* d_in, const int* in_sizes, int n_in,
                              void* d_out, int out_size)
{
    (void)in_sizes; (void)n_in; (void)out_size;

    const float* x_gene    = (const float*)d_in[0];
    const float* x_disease = (const float*)d_in[1];
    const int*   ei_g2d    = (const int*)d_in[2];
    const int*   ei_d2g    = (const int*)d_in[3];
    const int*   eli       = (const int*)d_in[6];
    const float* Wn_g      = (const float*)d_in[7];
    const float* bn_g      = (const float*)d_in[8];
    const float* Wn_d      = (const float*)d_in[9];
    const float* bn_d      = (const float*)d_in[10];
    const float* W1        = (const float*)d_in[17];
    const float* b1        = (const float*)d_in[18];
    const float* W2        = (const float*)d_in[19];
    const float* b2        = (const float*)d_in[20];

    float* out   = (float*)d_out;
    float* pred  = out;
    float* z_gen = out + NEL;
    float* z_dis = out + NEL + (size_t)NGN * CC;

    __nv_bfloat16* wimg;
    float* ug_ptr; float* ud_ptr;
    unsigned char* mg_ptr; unsigned char* md_ptr;
    cudaGetSymbolAddress((void**)&wimg,   g_wimg);
    cudaGetSymbolAddress((void**)&ug_ptr, g_ug);
    cudaGetSymbolAddress((void**)&ud_ptr, g_ud);
    cudaGetSymbolAddress((void**)&mg_ptr, g_mask_g);
    cudaGetSymbolAddress((void**)&md_ptr, g_mask_d);

    #define WIMG(m, h) (wimg + ((size_t)(m) * 2 + (h)) * TILE_IMG_ELEMS)

    cudaFuncSetAttribute(fused_gemm_kernel,
                         cudaFuncAttributeMaxDynamicSharedMemorySize, SMEM_TOTAL);

    // 1) isolation masks
    init_masks_kernel<<<(NGN + 255) / 256, 256>>>();
    scatter_masks_kernel<<<(NE + 255) / 256, 256>>>(ei_g2d + NE, ei_d2g + NE);

    // 2) weight split images (4 x 32KB, bf16 hi/lo, swizzled W^T)
    wsplit_kernel<<<4, 256>>>(Wn_g, Wn_d, W1);

    // 3) fused (z, u) per node type
    fused_gemm_kernel<<<TILES, 256, SMEM_TOTAL>>>(
        x_gene, WIMG(0, 0), WIMG(0, 1), WIMG(2, 0), WIMG(2, 1),
        bn_g, nullptr, mg_ptr, z_gen, ug_ptr, NGN);
    fused_gemm_kernel<<<TILES, 256, SMEM_TOTAL>>>(
        x_disease, WIMG(1, 0), WIMG(1, 1), WIMG(3, 0), WIMG(3, 1),
        bn_d, b1, md_ptr, z_dis, ud_ptr, NDN);

    // 4) edge scores
    pred_kernel<<<(NEL * 32 + 255) / 256, 256>>>(eli, eli + NEL, W2, b2, pred);
}